// round 1
// baseline (speedup 1.0000x reference)
#include <cuda_runtime.h>
#include <cuda_bf16.h>

// Problem constants (fixed by the reference)
#define A_N   100000
#define B_N   200000
#define M_N   20000
#define HDIM  256
#define MAXNB 10
#define NMOLS 2000
#define AFD   35
#define BFD   5
#define KI    (AFD + BFD)   // 40  : fbonds @ W_i
#define KO    (AFD + HDIM)  // 291 : [fatoms, nei] @ W_o_w

// Scratch (device globals — no allocation allowed in kernel_launch)
__device__ float g_binput[(size_t)B_N * HDIM];  // pre-relu bond input
__device__ float g_msg   [(size_t)B_N * HDIM];  // graph_message
__device__ float g_nei   [(size_t)B_N * HDIM];  // gathered neighbor sums (reused for atoms)
__device__ float g_counts[NMOLS];

// ---------------------------------------------------------------------------
// Gather + sum over MAX_NB neighbor rows of the virtual concat
// [tree_message (M rows) ; graph_message (B rows)], each row HDIM floats.
// blockDim = (64, 4): 64 lanes x float4 covers one 256-float row; 4 rows/block.
// ---------------------------------------------------------------------------
__global__ void gather_sum_kernel(const int* __restrict__ graph, int rows,
                                  const float* __restrict__ tree,
                                  const float* __restrict__ msg,
                                  float* __restrict__ out)
{
    int row = blockIdx.x * blockDim.y + threadIdx.y;
    if (row >= rows) return;
    int t = threadIdx.x;  // 0..63
    const int* gr = graph + (size_t)row * MAXNB;
    float4 acc = make_float4(0.f, 0.f, 0.f, 0.f);
#pragma unroll
    for (int j = 0; j < MAXNB; j++) {
        int idx = __ldg(&gr[j]);
        const float* srcp = (idx < M_N) ? (tree + (size_t)idx * HDIM)
                                        : (msg  + (size_t)(idx - M_N) * HDIM);
        float4 v = __ldg(((const float4*)srcp) + t);
        acc.x += v.x; acc.y += v.y; acc.z += v.z; acc.w += v.w;
    }
    ((float4*)(out + (size_t)row * HDIM))[t] = acc;
}

// ---------------------------------------------------------------------------
// Classic 128x128x8 register-tiled SGEMM, N fixed = HDIM = 256.
// MODE 0: C = fbonds @ W_i          -> out1 = C (binput), out2 = relu(C) (msg)
// MODE 1: C = nei   @ W_h           -> out1 = relu(binput + C) (msg)
// MODE 2: C = [fatoms, nei] @ W_o_w -> v = relu(C + bias); atomicAdd into
//            sums[scope[row]*H + col]
// ---------------------------------------------------------------------------
#define BM 128
#define BN 128
#define BK 8
#define TM 8
#define TN 8

template <int MODE>
__global__ __launch_bounds__(256)
void gemm_kernel(const float* __restrict__ Amat,   // fbonds / nei / fatoms
                 const float* __restrict__ A2,     // nei (MODE 2 only)
                 const float* __restrict__ Bmat,   // weight [K, 256] row-major
                 int rowsM, int Kdim,
                 const float* __restrict__ binput, // MODE 1
                 const float* __restrict__ bias,   // MODE 2
                 const int*   __restrict__ scope,  // MODE 2
                 float* __restrict__ out1,
                 float* __restrict__ out2)
{
    __shared__ float As[BK][BM];
    __shared__ float Bs[BK][BN];

    const int tid = threadIdx.x;              // 0..255
    const int rowBlock = blockIdx.y * BM;
    const int colBlock = blockIdx.x * BN;
    const int tr = tid / (BN / TN);           // 0..15
    const int tc = tid % (BN / TN);           // 0..15

    float acc[TM][TN];
#pragma unroll
    for (int i = 0; i < TM; i++)
#pragma unroll
        for (int j = 0; j < TN; j++) acc[i][j] = 0.f;

    for (int k0 = 0; k0 < Kdim; k0 += BK) {
        // Load A tile (BM x BK), store transposed As[k][m]
#pragma unroll
        for (int it = 0; it < 4; it++) {
            int li = it * 256 + tid;
            int r  = li / BK;
            int kk = li % BK;
            int grow = rowBlock + r;
            int gk   = k0 + kk;
            float v = 0.f;
            if (grow < rowsM && gk < Kdim) {
                if (MODE == 2) {
                    v = (gk < AFD) ? __ldg(&Amat[(size_t)grow * AFD + gk])
                                   : __ldg(&A2[(size_t)grow * HDIM + (gk - AFD)]);
                } else {
                    v = __ldg(&Amat[(size_t)grow * Kdim + gk]);
                }
            }
            As[kk][r] = v;
        }
        // Load B tile (BK x BN) — coalesced along N
#pragma unroll
        for (int it = 0; it < 4; it++) {
            int li = it * 256 + tid;
            int r = li / BN;
            int c = li % BN;
            int gk = k0 + r;
            Bs[r][c] = (gk < Kdim) ? __ldg(&Bmat[(size_t)gk * HDIM + colBlock + c]) : 0.f;
        }
        __syncthreads();

#pragma unroll
        for (int kk = 0; kk < BK; kk++) {
            float ar[TM], br[TN];
            // vectorized smem reads (8 consecutive floats -> 2x float4)
            const float4* ap = (const float4*)&As[kk][tr * TM];
            float4 a0 = ap[0], a1 = ap[1];
            ar[0]=a0.x; ar[1]=a0.y; ar[2]=a0.z; ar[3]=a0.w;
            ar[4]=a1.x; ar[5]=a1.y; ar[6]=a1.z; ar[7]=a1.w;
            const float4* bp = (const float4*)&Bs[kk][tc * TN];
            float4 b0 = bp[0], b1 = bp[1];
            br[0]=b0.x; br[1]=b0.y; br[2]=b0.z; br[3]=b0.w;
            br[4]=b1.x; br[5]=b1.y; br[6]=b1.z; br[7]=b1.w;
#pragma unroll
            for (int i = 0; i < TM; i++)
#pragma unroll
                for (int j = 0; j < TN; j++)
                    acc[i][j] += ar[i] * br[j];
        }
        __syncthreads();
    }

    // Epilogue
#pragma unroll
    for (int i = 0; i < TM; i++) {
        int grow = rowBlock + tr * TM + i;
        if (grow >= rowsM) continue;
        int seg = 0;
        if (MODE == 2) seg = __ldg(&scope[grow]);
#pragma unroll
        for (int j = 0; j < TN; j++) {
            int col = colBlock + tc * TN + j;
            float c = acc[i][j];
            if (MODE == 0) {
                out1[(size_t)grow * HDIM + col] = c;
                out2[(size_t)grow * HDIM + col] = fmaxf(c, 0.f);
            } else if (MODE == 1) {
                float v = __ldg(&binput[(size_t)grow * HDIM + col]) + c;
                out1[(size_t)grow * HDIM + col] = fmaxf(v, 0.f);
            } else {
                float v = fmaxf(c + __ldg(&bias[col]), 0.f);
                atomicAdd(&out1[(size_t)seg * HDIM + col], v);
            }
        }
    }
}

// ---------------------------------------------------------------------------
// Pooling helpers
// ---------------------------------------------------------------------------
__global__ void zero_out_kernel(float* __restrict__ out)
{
    int i = blockIdx.x * blockDim.x + threadIdx.x;
    if (i < NMOLS * HDIM) out[i] = 0.f;
    if (i < NMOLS) g_counts[i] = 0.f;
}

__global__ void count_kernel(const int* __restrict__ scope)
{
    int i = blockIdx.x * blockDim.x + threadIdx.x;
    if (i < A_N) atomicAdd(&g_counts[__ldg(&scope[i])], 1.f);
}

__global__ void finalize_kernel(float* __restrict__ out)
{
    int i = blockIdx.x * blockDim.x + threadIdx.x;
    if (i >= NMOLS * HDIM) return;
    int m = i / HDIM;
    out[i] = out[i] / fmaxf(g_counts[m], 1.f);
}

// ---------------------------------------------------------------------------
extern "C" void kernel_launch(void* const* d_in, const int* in_sizes, int n_in,
                              void* d_out, int out_size)
{
    const float* fatoms   = (const float*)d_in[0];
    const float* fbonds   = (const float*)d_in[1];
    const int*   agraph   = (const int*)  d_in[2];
    const int*   bgraph   = (const int*)  d_in[3];
    const float* tree_msg = (const float*)d_in[4];
    const int*   scope    = (const int*)  d_in[5];
    const float* W_i      = (const float*)d_in[6];
    const float* W_h      = (const float*)d_in[7];
    const float* W_o_w    = (const float*)d_in[8];
    const float* W_o_b    = (const float*)d_in[9];
    float* out = (float*)d_out;

    float *binput, *msg, *nei;
    cudaGetSymbolAddress((void**)&binput, g_binput);
    cudaGetSymbolAddress((void**)&msg,    g_msg);
    cudaGetSymbolAddress((void**)&nei,    g_nei);

    dim3 blk(256);
    dim3 grid_b(HDIM / BN, (B_N + BM - 1) / BM);
    dim3 grid_a(HDIM / BN, (A_N + BM - 1) / BM);

    // 1) binput = fbonds @ W_i ; msg = relu(binput)
    gemm_kernel<0><<<grid_b, blk>>>(fbonds, nullptr, W_i, B_N, KI,
                                    nullptr, nullptr, nullptr, binput, msg);

    // 2) two message-passing iterations
    dim3 gblk(64, 4);
    for (int d = 0; d < 2; d++) {
        gather_sum_kernel<<<(B_N + 3) / 4, gblk>>>(bgraph, B_N, tree_msg, msg, nei);
        gemm_kernel<1><<<grid_b, blk>>>(nei, nullptr, W_h, B_N, HDIM,
                                        binput, nullptr, nullptr, msg, nullptr);
    }

    // 3) atom neighbor gather (reuse nei buffer: A_N*H <= B_N*H)
    gather_sum_kernel<<<(A_N + 3) / 4, gblk>>>(agraph, A_N, tree_msg, msg, nei);

    // 4) pooling: zero sums + counts, count atoms, GEMM3 w/ fused atomic segment-sum
    zero_out_kernel<<<(NMOLS * HDIM + 255) / 256, 256>>>(out);
    count_kernel<<<(A_N + 255) / 256, 256>>>(scope);
    gemm_kernel<2><<<grid_a, blk>>>(fatoms, nei, W_o_w, A_N, KO,
                                    nullptr, W_o_b, scope, out, nullptr);
    finalize_kernel<<<(NMOLS * HDIM + 255) / 256, 256>>>(out);
}

// round 2
// speedup vs baseline: 1.1371x; 1.1371x over previous
#include <cuda_runtime.h>
#include <cuda_bf16.h>

// Problem constants (fixed by the reference)
#define A_N   100000
#define B_N   200000
#define M_N   20000
#define HDIM  256
#define MAXNB 10
#define NMOLS 2000
#define AFD   35
#define BFD   5
#define KI    (AFD + BFD)   // 40  : fbonds @ W_i
#define KO    (AFD + HDIM)  // 291 : [fatoms, nei] @ W_o_w

// Scratch (device globals — no allocation allowed in kernel_launch)
__device__ float g_binput[(size_t)B_N * HDIM];
__device__ float g_msg   [(size_t)B_N * HDIM];
__device__ float g_nei   [(size_t)B_N * HDIM];
__device__ float g_counts[NMOLS];

typedef unsigned long long u64;

__device__ __forceinline__ u64 pack2(float x, float y) {
    u64 r; asm("mov.b64 %0, {%1,%2};" : "=l"(r) : "f"(x), "f"(y)); return r;
}
__device__ __forceinline__ float2 unpack2(u64 v) {
    float2 r; asm("mov.b64 {%0,%1}, %2;" : "=f"(r.x), "=f"(r.y) : "l"(v)); return r;
}
__device__ __forceinline__ void fma2(u64& d, u64 a, u64 b) {
    asm("fma.rn.f32x2 %0, %1, %2, %0;" : "+l"(d) : "l"(a), "l"(b));
}

// ---------------------------------------------------------------------------
// Gather + sum over MAX_NB neighbor rows of virtual concat [tree ; msg].
// At HBM roofline (87% DRAM) — unchanged.
// ---------------------------------------------------------------------------
__global__ void gather_sum_kernel(const int* __restrict__ graph, int rows,
                                  const float* __restrict__ tree,
                                  const float* __restrict__ msg,
                                  float* __restrict__ out)
{
    int row = blockIdx.x * blockDim.y + threadIdx.y;
    if (row >= rows) return;
    int t = threadIdx.x;  // 0..63
    const int* gr = graph + (size_t)row * MAXNB;
    float4 acc = make_float4(0.f, 0.f, 0.f, 0.f);
#pragma unroll
    for (int j = 0; j < MAXNB; j++) {
        int idx = __ldg(&gr[j]);
        const float* srcp = (idx < M_N) ? (tree + (size_t)idx * HDIM)
                                        : (msg  + (size_t)(idx - M_N) * HDIM);
        float4 v = __ldg(((const float4*)srcp) + t);
        acc.x += v.x; acc.y += v.y; acc.z += v.z; acc.w += v.w;
    }
    ((float4*)(out + (size_t)row * HDIM))[t] = acc;
}

// ---------------------------------------------------------------------------
// 128x128x16 register-tiled SGEMM using packed fma.rn.f32x2 (FFMA2).
// Accumulators are f32x2 pairs along the M dimension: rows (2*i2, 2*i2+1)
// come straight out of the transposed As tile as one LDS.64.
// MODE 0: C = fbonds @ W_i          -> out1 = C, out2 = relu(C)
// MODE 1: C = nei   @ W_h           -> out1 = relu(binput + C)
// MODE 2: C = [fatoms, nei] @ W_o_w -> relu(C + bias) atomicAdd'ed into segments
// ---------------------------------------------------------------------------
#define BM 128
#define BN 128
#define BK 16
#define TM 8
#define TN 8

template <int MODE>
__global__ __launch_bounds__(256)
void gemm_kernel(const float* __restrict__ Amat,
                 const float* __restrict__ A2,
                 const float* __restrict__ Bmat,   // [K, 256] row-major
                 int rowsM, int Kdim,
                 const float* __restrict__ binput,
                 const float* __restrict__ bias,
                 const int*   __restrict__ scope,
                 float* __restrict__ out1,
                 float* __restrict__ out2)
{
    __shared__ float As[BK][BM];
    __shared__ float Bs[BK][BN];

    const int tid = threadIdx.x;              // 0..255
    const int rowBlock = blockIdx.y * BM;
    const int colBlock = blockIdx.x * BN;
    const int tr = tid / (BN / TN);           // 0..15
    const int tc = tid % (BN / TN);           // 0..15

    u64 acc2[TM / 2][TN];                     // pairs along M: 32 x f32x2
#pragma unroll
    for (int i = 0; i < TM / 2; i++)
#pragma unroll
        for (int j = 0; j < TN; j++) acc2[i][j] = 0ull;

    for (int k0 = 0; k0 < Kdim; k0 += BK) {
        // Load A tile (BM x BK) transposed: As[k][m]
#pragma unroll
        for (int it = 0; it < (BM * BK) / 256; it++) {
            int li = it * 256 + tid;
            int r  = li / BK;
            int kk = li % BK;
            int grow = rowBlock + r;
            int gk   = k0 + kk;
            float v = 0.f;
            if (grow < rowsM && gk < Kdim) {
                if (MODE == 2) {
                    v = (gk < AFD) ? __ldg(&Amat[(size_t)grow * AFD + gk])
                                   : __ldg(&A2[(size_t)grow * HDIM + (gk - AFD)]);
                } else {
                    v = __ldg(&Amat[(size_t)grow * Kdim + gk]);
                }
            }
            As[kk][r] = v;
        }
        // Load B tile (BK x BN) — coalesced along N
#pragma unroll
        for (int it = 0; it < (BK * BN) / 256; it++) {
            int li = it * 256 + tid;
            int r = li / BN;
            int c = li % BN;
            int gk = k0 + r;
            Bs[r][c] = (gk < Kdim) ? __ldg(&Bmat[(size_t)gk * HDIM + colBlock + c]) : 0.f;
        }
        __syncthreads();

#pragma unroll
        for (int kk = 0; kk < BK; kk++) {
            // A: 4 packed row-pairs, directly from smem (LDS.64)
            const u64* ap = (const u64*)&As[kk][tr * TM];
            u64 a0 = ap[0], a1 = ap[1], a2 = ap[2], a3 = ap[3];
            // B: 8 scalars, broadcast-packed
            const float4* bp = (const float4*)&Bs[kk][tc * TN];
            float4 b0 = bp[0], b1 = bp[1];
            u64 bb[TN];
            bb[0] = pack2(b0.x, b0.x); bb[1] = pack2(b0.y, b0.y);
            bb[2] = pack2(b0.z, b0.z); bb[3] = pack2(b0.w, b0.w);
            bb[4] = pack2(b1.x, b1.x); bb[5] = pack2(b1.y, b1.y);
            bb[6] = pack2(b1.z, b1.z); bb[7] = pack2(b1.w, b1.w);
#pragma unroll
            for (int j = 0; j < TN; j++) {
                fma2(acc2[0][j], a0, bb[j]);
                fma2(acc2[1][j], a1, bb[j]);
                fma2(acc2[2][j], a2, bb[j]);
                fma2(acc2[3][j], a3, bb[j]);
            }
        }
        __syncthreads();
    }

    // Epilogue — vectorized STG.128 along the 8 contiguous columns per thread
#pragma unroll
    for (int half = 0; half < 2; half++) {   // lo/hi of the f32x2 pairs
#pragma unroll
        for (int i2 = 0; i2 < TM / 2; i2++) {
            int grow = rowBlock + tr * TM + 2 * i2 + half;
            if (grow >= rowsM) continue;
            float c[TN];
#pragma unroll
            for (int j = 0; j < TN; j++) {
                float2 v = unpack2(acc2[i2][j]);
                c[j] = half ? v.y : v.x;
            }
            int col0 = colBlock + tc * TN;
            size_t base = (size_t)grow * HDIM + col0;
            if (MODE == 0) {
                ((float4*)(out1 + base))[0] = make_float4(c[0], c[1], c[2], c[3]);
                ((float4*)(out1 + base))[1] = make_float4(c[4], c[5], c[6], c[7]);
                ((float4*)(out2 + base))[0] = make_float4(fmaxf(c[0],0.f), fmaxf(c[1],0.f),
                                                          fmaxf(c[2],0.f), fmaxf(c[3],0.f));
                ((float4*)(out2 + base))[1] = make_float4(fmaxf(c[4],0.f), fmaxf(c[5],0.f),
                                                          fmaxf(c[6],0.f), fmaxf(c[7],0.f));
            } else if (MODE == 1) {
                float4 p0 = __ldg((const float4*)(binput + base));
                float4 p1 = __ldg((const float4*)(binput + base) + 1);
                ((float4*)(out1 + base))[0] = make_float4(fmaxf(c[0]+p0.x,0.f), fmaxf(c[1]+p0.y,0.f),
                                                          fmaxf(c[2]+p0.z,0.f), fmaxf(c[3]+p0.w,0.f));
                ((float4*)(out1 + base))[1] = make_float4(fmaxf(c[4]+p1.x,0.f), fmaxf(c[5]+p1.y,0.f),
                                                          fmaxf(c[6]+p1.z,0.f), fmaxf(c[7]+p1.w,0.f));
            } else {
                int seg = __ldg(&scope[grow]);
#pragma unroll
                for (int j = 0; j < TN; j++) {
                    float v = fmaxf(c[j] + __ldg(&bias[col0 + j]), 0.f);
                    atomicAdd(&out1[(size_t)seg * HDIM + col0 + j], v);
                }
            }
        }
    }
}

// ---------------------------------------------------------------------------
// Pooling helpers
// ---------------------------------------------------------------------------
__global__ void zero_out_kernel(float* __restrict__ out)
{
    int i = blockIdx.x * blockDim.x + threadIdx.x;
    if (i < NMOLS * HDIM) out[i] = 0.f;
    if (i < NMOLS) g_counts[i] = 0.f;
}

__global__ void count_kernel(const int* __restrict__ scope)
{
    int i = blockIdx.x * blockDim.x + threadIdx.x;
    if (i < A_N) atomicAdd(&g_counts[__ldg(&scope[i])], 1.f);
}

__global__ void finalize_kernel(float* __restrict__ out)
{
    int i = blockIdx.x * blockDim.x + threadIdx.x;
    if (i >= NMOLS * HDIM) return;
    int m = i / HDIM;
    out[i] = out[i] / fmaxf(g_counts[m], 1.f);
}

// ---------------------------------------------------------------------------
extern "C" void kernel_launch(void* const* d_in, const int* in_sizes, int n_in,
                              void* d_out, int out_size)
{
    const float* fatoms   = (const float*)d_in[0];
    const float* fbonds   = (const float*)d_in[1];
    const int*   agraph   = (const int*)  d_in[2];
    const int*   bgraph   = (const int*)  d_in[3];
    const float* tree_msg = (const float*)d_in[4];
    const int*   scope    = (const int*)  d_in[5];
    const float* W_i      = (const float*)d_in[6];
    const float* W_h      = (const float*)d_in[7];
    const float* W_o_w    = (const float*)d_in[8];
    const float* W_o_b    = (const float*)d_in[9];
    float* out = (float*)d_out;

    float *binput, *msg, *nei;
    cudaGetSymbolAddress((void**)&binput, g_binput);
    cudaGetSymbolAddress((void**)&msg,    g_msg);
    cudaGetSymbolAddress((void**)&nei,    g_nei);

    dim3 blk(256);
    dim3 grid_b(HDIM / BN, (B_N + BM - 1) / BM);
    dim3 grid_a(HDIM / BN, (A_N + BM - 1) / BM);

    // 1) binput = fbonds @ W_i ; msg = relu(binput)
    gemm_kernel<0><<<grid_b, blk>>>(fbonds, nullptr, W_i, B_N, KI,
                                    nullptr, nullptr, nullptr, binput, msg);

    // 2) two message-passing iterations
    dim3 gblk(64, 4);
    for (int d = 0; d < 2; d++) {
        gather_sum_kernel<<<(B_N + 3) / 4, gblk>>>(bgraph, B_N, tree_msg, msg, nei);
        gemm_kernel<1><<<grid_b, blk>>>(nei, nullptr, W_h, B_N, HDIM,
                                        binput, nullptr, nullptr, msg, nullptr);
    }

    // 3) atom neighbor gather (reuse nei buffer: A_N*H <= B_N*H)
    gather_sum_kernel<<<(A_N + 3) / 4, gblk>>>(agraph, A_N, tree_msg, msg, nei);

    // 4) pooling: zero sums + counts, count atoms, GEMM3 w/ fused atomic segment-sum
    zero_out_kernel<<<(NMOLS * HDIM + 255) / 256, 256>>>(out);
    count_kernel<<<(A_N + 255) / 256, 256>>>(scope);
    gemm_kernel<2><<<grid_a, blk>>>(fatoms, nei, W_o_w, A_N, KO,
                                    nullptr, W_o_b, scope, out, nullptr);
    finalize_kernel<<<(NMOLS * HDIM + 255) / 256, 256>>>(out);
}

// round 4
// speedup vs baseline: 2.0654x; 1.8164x over previous
#include <cuda_runtime.h>
#include <cuda_bf16.h>
#include <cstdint>

// Problem constants
#define A_N   100000
#define B_N   200000
#define M_N   20000
#define HDIM  256
#define MAXNB 10
#define NMOLS 2000
#define AFD   35
#define KI    40    // fbonds @ W_i
#define KO    291   // [fatoms, nei] @ W_o_w

// Scratch (device globals)
__device__ float g_binput[(size_t)B_N * HDIM];
__device__ float g_msg   [(size_t)B_N * HDIM];
__device__ float g_nei   [(size_t)B_N * HDIM];
__device__ float g_counts[NMOLS];
// Pre-transposed, bf16-split weights: [N=256, KPAD<=320]
__device__ __nv_bfloat16 g_WThi[256 * 320];
__device__ __nv_bfloat16 g_WTlo[256 * 320];

// ---------------------------------------------------------------------------
// Helpers (all base-sm_103-legal: ldmatrix / mma.sync / cp.async)
// ---------------------------------------------------------------------------
__device__ __forceinline__ uint32_t smem_u32(const void* p) {
    uint32_t a;
    asm("{ .reg .u64 t; cvta.to.shared.u64 t, %1; cvt.u32.u64 %0, t; }" : "=r"(a) : "l"(p));
    return a;
}
__device__ __forceinline__ void ldsm4(uint32_t* r, uint32_t addr) {
    asm volatile("ldmatrix.sync.aligned.m8n8.x4.shared.b16 {%0,%1,%2,%3}, [%4];"
                 : "=r"(r[0]), "=r"(r[1]), "=r"(r[2]), "=r"(r[3]) : "r"(addr));
}
__device__ __forceinline__ void mma_bf16(float* c, const uint32_t* a, uint32_t b0, uint32_t b1) {
    asm volatile("mma.sync.aligned.m16n8k16.row.col.f32.bf16.bf16.f32 "
                 "{%0,%1,%2,%3},{%4,%5,%6,%7},{%8,%9},{%0,%1,%2,%3};"
                 : "+f"(c[0]), "+f"(c[1]), "+f"(c[2]), "+f"(c[3])
                 : "r"(a[0]), "r"(a[1]), "r"(a[2]), "r"(a[3]), "r"(b0), "r"(b1));
}
__device__ __forceinline__ void cp_async16(uint32_t dst, const void* src) {
    asm volatile("cp.async.cg.shared.global [%0], [%1], 16;" :: "r"(dst), "l"(src));
}
__device__ __forceinline__ void cp_wait_all() {
    asm volatile("cp.async.wait_all;" ::: "memory");
}

#define SW128(o) ((o) ^ ((((uint32_t)(o)) >> 3) & 0x70))

__device__ __forceinline__ void split2(float v, unsigned short& h, unsigned short& l) {
    __nv_bfloat16 hb = __float2bfloat16_rn(v);
    float rem = v - __bfloat162float(hb);
    h = __bfloat16_as_ushort(hb);
    l = __bfloat16_as_ushort(__float2bfloat16_rn(rem));
}

// ---------------------------------------------------------------------------
// Gather + sum over MAX_NB neighbor rows of virtual concat [tree ; msg].
// At HBM roofline — unchanged.
// ---------------------------------------------------------------------------
__global__ void gather_sum_kernel(const int* __restrict__ graph, int rows,
                                  const float* __restrict__ tree,
                                  const float* __restrict__ msg,
                                  float* __restrict__ out)
{
    int row = blockIdx.x * blockDim.y + threadIdx.y;
    if (row >= rows) return;
    int t = threadIdx.x;
    const int* gr = graph + (size_t)row * MAXNB;
    float4 acc = make_float4(0.f, 0.f, 0.f, 0.f);
#pragma unroll
    for (int j = 0; j < MAXNB; j++) {
        int idx = __ldg(&gr[j]);
        const float* srcp = (idx < M_N) ? (tree + (size_t)idx * HDIM)
                                        : (msg  + (size_t)(idx - M_N) * HDIM);
        float4 v = __ldg(((const float4*)srcp) + t);
        acc.x += v.x; acc.y += v.y; acc.z += v.z; acc.w += v.w;
    }
    ((float4*)(out + (size_t)row * HDIM))[t] = acc;
}

// ---------------------------------------------------------------------------
// Weight prep: W [Kdim, 256] fp32 -> WT hi/lo bf16 [256, Kpad] (zero padded)
// ---------------------------------------------------------------------------
__global__ void prep_w_kernel(const float* __restrict__ W, int Kdim, int Kpad,
                              __nv_bfloat16* __restrict__ hi, __nv_bfloat16* __restrict__ lo)
{
    int i = blockIdx.x * blockDim.x + threadIdx.x;
    if (i >= 256 * Kpad) return;
    int n = i / Kpad, k = i % Kpad;
    float v = (k < Kdim) ? __ldg(&W[(size_t)k * 256 + n]) : 0.f;
    unsigned short h, l; split2(v, h, l);
    hi[i] = __ushort_as_bfloat16(h);
    lo[i] = __ushort_as_bfloat16(l);
}

// ---------------------------------------------------------------------------
// bf16 3-split GEMM via mma.sync: C[128,256] = A[128,KDIM] @ W[KDIM,256].
// 8 warps, 2x4 warp grid, 64x64 warp tile, K chunks of 64, double-buffered
// SW128 smem; B via cp.async; A LDG->split->STS. fp32 accumulate in regs.
// MODE 0: A=fbonds       -> out1 = C, out2 = relu(C)
// MODE 1: A=nei          -> out1 = relu(binput + C)
// MODE 2: A=[fatoms|nei] -> relu(C + bias) atomicAdd into out1[scope[row]]
// ---------------------------------------------------------------------------
#define OFF_ALO  16384
#define OFF_BHI  32768
#define OFF_BLO  65536
#define BUFSZ    98304
#define HG_SMEM  (2 * BUFSZ)   // 196608

template <int MODE, int KDIM, int NS>
__global__ __launch_bounds__(256, 1)
void hgemm_kernel(const float* __restrict__ Amat,
                  const float* __restrict__ A2,
                  const __nv_bfloat16* __restrict__ WThi,
                  const __nv_bfloat16* __restrict__ WTlo,
                  int rowsM,
                  const float* __restrict__ binput,
                  const float* __restrict__ bias,
                  const int*   __restrict__ scope,
                  float* __restrict__ out1,
                  float* __restrict__ out2)
{
    constexpr int KPAD = NS * 64;
    extern __shared__ char smem[];
    const uint32_t sb = smem_u32(smem);
    const int tid  = threadIdx.x;
    const int lane = tid & 31, wid = tid >> 5;
    const int wm = wid & 1, wn = wid >> 1;           // 2 x 4 warp grid
    const int rowBlock = blockIdx.x * 128;
    const int r    = tid >> 1;                        // A-load row (0..127)
    const int half = tid & 1;                         // A-load col half

    // ldmatrix lane-address components
    const int arow  = ((lane >> 3) & 1) * 8 + (lane & 7);
    const int akb   = (lane >> 4) * 16;
    const int bnrow = ((lane >> 4) & 1) * 8 + (lane & 7);
    const int bkb   = ((lane >> 3) & 1) * 16;

    float acc[4][8][4];
#pragma unroll
    for (int mi = 0; mi < 4; mi++)
#pragma unroll
        for (int ni = 0; ni < 8; ni++)
#pragma unroll
            for (int e = 0; e < 4; e++) acc[mi][ni][e] = 0.f;

    float4 af[8];

    auto ldgA = [&](int s) {
        int k0 = s * 64;
        int gr = rowBlock + r;
#pragma unroll
        for (int j = 0; j < 8; j++) {
            int gc = k0 + half * 32 + j * 4;
            float4 v = make_float4(0.f, 0.f, 0.f, 0.f);
            if (gr < rowsM) {
                if (MODE == 2) {
                    float t0 = 0.f, t1 = 0.f, t2 = 0.f, t3 = 0.f;
#pragma unroll
                    for (int e = 0; e < 4; e++) {
                        int gk = gc + e;
                        float x = 0.f;
                        if (gk < AFD)     x = __ldg(&Amat[(size_t)gr * AFD + gk]);
                        else if (gk < KO) x = __ldg(&A2[(size_t)gr * HDIM + (gk - AFD)]);
                        if (e == 0) t0 = x; else if (e == 1) t1 = x; else if (e == 2) t2 = x; else t3 = x;
                    }
                    v = make_float4(t0, t1, t2, t3);
                } else {
                    if (gc < KDIM)
                        v = __ldg((const float4*)(Amat + (size_t)gr * KDIM + gc));
                }
            }
            af[j] = v;
        }
    };

    auto stsA = [&](uint32_t bufOff) {
#pragma unroll
        for (int j = 0; j < 8; j++) {
            unsigned short h0, h1, h2, h3, l0, l1, l2, l3;
            split2(af[j].x, h0, l0); split2(af[j].y, h1, l1);
            split2(af[j].z, h2, l2); split2(af[j].w, h3, l3);
            uint2 uh, ul;
            uh.x = (uint32_t)h0 | ((uint32_t)h1 << 16);
            uh.y = (uint32_t)h2 | ((uint32_t)h3 << 16);
            ul.x = (uint32_t)l0 | ((uint32_t)l1 << 16);
            ul.y = (uint32_t)l2 | ((uint32_t)l3 << 16);
            uint32_t off = SW128(r * 128 + half * 64 + j * 8);
            *(uint2*)(smem + bufOff + off)           = uh;
            *(uint2*)(smem + bufOff + OFF_ALO + off) = ul;
        }
    };

    auto cpB = [&](int s) {
        int k0 = s * 64;
        uint32_t bufOff = (uint32_t)(s & 1) * BUFSZ;
#pragma unroll
        for (int i = 0; i < 8; i++) {
            int idx = i * 256 + tid;
            int n = idx >> 3, c = idx & 7;
            uint32_t dsw = SW128(n * 128 + c * 16);
            const __nv_bfloat16* srch = WThi + (size_t)n * KPAD + k0 + c * 8;
            const __nv_bfloat16* srcl = WTlo + (size_t)n * KPAD + k0 + c * 8;
            cp_async16(sb + bufOff + OFF_BHI + dsw, srch);
            cp_async16(sb + bufOff + OFF_BLO + dsw, srcl);
        }
    };

    // Prologue
    ldgA(0);
    cpB(0);

    for (int s = 0; s < NS; s++) {
        uint32_t bufOff = (uint32_t)(s & 1) * BUFSZ;
        cp_wait_all();              // B(s) arrived (own async ops)
        stsA(bufOff);
        __syncthreads();            // smem tile (A sts + B cp.async) visible to all
        if (s + 1 < NS) { cpB(s + 1); ldgA(s + 1); }

        const uint32_t aBase = sb + bufOff;
#pragma unroll
        for (int kk = 0; kk < 4; kk++) {
            uint32_t ahi[4][4], alo[4][4];
#pragma unroll
            for (int mi = 0; mi < 4; mi++) {
                uint32_t off = (uint32_t)(wm * 64 + mi * 16 + arow) * 128 + kk * 32 + akb;
                uint32_t sw = SW128(off);
                ldsm4(ahi[mi], aBase + sw);
                ldsm4(alo[mi], aBase + OFF_ALO + sw);
            }
#pragma unroll
            for (int nb = 0; nb < 4; nb++) {
                uint32_t off = (uint32_t)(wn * 64 + nb * 16 + bnrow) * 128 + kk * 32 + bkb;
                uint32_t sw = SW128(off);
                uint32_t bh[4], bl[4];
                ldsm4(bh, aBase + OFF_BHI + sw);
                ldsm4(bl, aBase + OFF_BLO + sw);
#pragma unroll
                for (int mi = 0; mi < 4; mi++) {
                    mma_bf16(acc[mi][2*nb],   ahi[mi], bh[0], bh[1]);
                    mma_bf16(acc[mi][2*nb+1], ahi[mi], bh[2], bh[3]);
                    mma_bf16(acc[mi][2*nb],   alo[mi], bh[0], bh[1]);
                    mma_bf16(acc[mi][2*nb+1], alo[mi], bh[2], bh[3]);
                    mma_bf16(acc[mi][2*nb],   ahi[mi], bl[0], bl[1]);
                    mma_bf16(acc[mi][2*nb+1], ahi[mi], bl[2], bl[3]);
                }
            }
        }
        // no trailing sync needed: next iter's barrier separates buffers
    }

    // ---- Epilogue: acc in registers ----
#pragma unroll
    for (int mi = 0; mi < 4; mi++) {
        int r0 = rowBlock + wm * 64 + mi * 16 + (lane >> 2);
        int r1 = r0 + 8;
        int seg0 = 0, seg1 = 0;
        if (MODE == 2) {
            seg0 = (r0 < rowsM) ? __ldg(&scope[r0]) : 0;
            seg1 = (r1 < rowsM) ? __ldg(&scope[r1]) : 0;
        }
#pragma unroll
        for (int ni = 0; ni < 8; ni++) {
            int col = wn * 64 + ni * 8 + (lane & 3) * 2;
            float* c = acc[mi][ni];
            if (MODE == 0) {
                if (r0 < rowsM) {
                    size_t p = (size_t)r0 * HDIM + col;
                    *(float2*)(out1 + p) = make_float2(c[0], c[1]);
                    *(float2*)(out2 + p) = make_float2(fmaxf(c[0],0.f), fmaxf(c[1],0.f));
                }
                if (r1 < rowsM) {
                    size_t p = (size_t)r1 * HDIM + col;
                    *(float2*)(out1 + p) = make_float2(c[2], c[3]);
                    *(float2*)(out2 + p) = make_float2(fmaxf(c[2],0.f), fmaxf(c[3],0.f));
                }
            } else if (MODE == 1) {
                if (r0 < rowsM) {
                    size_t p = (size_t)r0 * HDIM + col;
                    float2 b = *(const float2*)(binput + p);
                    *(float2*)(out1 + p) = make_float2(fmaxf(c[0]+b.x,0.f), fmaxf(c[1]+b.y,0.f));
                }
                if (r1 < rowsM) {
                    size_t p = (size_t)r1 * HDIM + col;
                    float2 b = *(const float2*)(binput + p);
                    *(float2*)(out1 + p) = make_float2(fmaxf(c[2]+b.x,0.f), fmaxf(c[3]+b.y,0.f));
                }
            } else {
                float b0 = __ldg(&bias[col]), b1 = __ldg(&bias[col + 1]);
                if (r0 < rowsM) {
                    atomicAdd(&out1[(size_t)seg0 * HDIM + col],     fmaxf(c[0] + b0, 0.f));
                    atomicAdd(&out1[(size_t)seg0 * HDIM + col + 1], fmaxf(c[1] + b1, 0.f));
                }
                if (r1 < rowsM) {
                    atomicAdd(&out1[(size_t)seg1 * HDIM + col],     fmaxf(c[2] + b0, 0.f));
                    atomicAdd(&out1[(size_t)seg1 * HDIM + col + 1], fmaxf(c[3] + b1, 0.f));
                }
            }
        }
    }
}

// ---------------------------------------------------------------------------
// Pooling helpers
// ---------------------------------------------------------------------------
__global__ void zero_out_kernel(float* __restrict__ out)
{
    int i = blockIdx.x * blockDim.x + threadIdx.x;
    if (i < NMOLS * HDIM) out[i] = 0.f;
    if (i < NMOLS) g_counts[i] = 0.f;
}
__global__ void count_kernel(const int* __restrict__ scope)
{
    int i = blockIdx.x * blockDim.x + threadIdx.x;
    if (i < A_N) atomicAdd(&g_counts[__ldg(&scope[i])], 1.f);
}
__global__ void finalize_kernel(float* __restrict__ out)
{
    int i = blockIdx.x * blockDim.x + threadIdx.x;
    if (i >= NMOLS * HDIM) return;
    out[i] = out[i] / fmaxf(g_counts[i / HDIM], 1.f);
}

// ---------------------------------------------------------------------------
extern "C" void kernel_launch(void* const* d_in, const int* in_sizes, int n_in,
                              void* d_out, int out_size)
{
    const float* fatoms   = (const float*)d_in[0];
    const float* fbonds   = (const float*)d_in[1];
    const int*   agraph   = (const int*)  d_in[2];
    const int*   bgraph   = (const int*)  d_in[3];
    const float* tree_msg = (const float*)d_in[4];
    const int*   scope    = (const int*)  d_in[5];
    const float* W_i      = (const float*)d_in[6];
    const float* W_h      = (const float*)d_in[7];
    const float* W_o_w    = (const float*)d_in[8];
    const float* W_o_b    = (const float*)d_in[9];
    float* out = (float*)d_out;

    float *binput, *msg, *nei;
    __nv_bfloat16 *wthi, *wtlo;
    cudaGetSymbolAddress((void**)&binput, g_binput);
    cudaGetSymbolAddress((void**)&msg,    g_msg);
    cudaGetSymbolAddress((void**)&nei,    g_nei);
    cudaGetSymbolAddress((void**)&wthi,   g_WThi);
    cudaGetSymbolAddress((void**)&wtlo,   g_WTlo);

    cudaFuncSetAttribute(hgemm_kernel<0, KI,   1>, cudaFuncAttributeMaxDynamicSharedMemorySize, HG_SMEM);
    cudaFuncSetAttribute(hgemm_kernel<1, HDIM, 4>, cudaFuncAttributeMaxDynamicSharedMemorySize, HG_SMEM);
    cudaFuncSetAttribute(hgemm_kernel<2, KO,   5>, cudaFuncAttributeMaxDynamicSharedMemorySize, HG_SMEM);

    const int gridB = (B_N + 127) / 128;   // 1563
    const int gridA = (A_N + 127) / 128;   // 782
    dim3 gblk(64, 4);

    // 1) binput = fbonds @ W_i ; msg = relu(binput)
    prep_w_kernel<<<(256 * 64 + 255) / 256, 256>>>(W_i, KI, 64, wthi, wtlo);
    hgemm_kernel<0, KI, 1><<<gridB, 256, HG_SMEM>>>(fbonds, nullptr, wthi, wtlo, B_N,
                                                    nullptr, nullptr, nullptr, binput, msg);

    // 2) two message-passing iterations (W_h prepped once)
    prep_w_kernel<<<(256 * 256 + 255) / 256, 256>>>(W_h, HDIM, 256, wthi, wtlo);
    for (int d = 0; d < 2; d++) {
        gather_sum_kernel<<<(B_N + 3) / 4, gblk>>>(bgraph, B_N, tree_msg, msg, nei);
        hgemm_kernel<1, HDIM, 4><<<gridB, 256, HG_SMEM>>>(nei, nullptr, wthi, wtlo, B_N,
                                                          binput, nullptr, nullptr, msg, nullptr);
    }

    // 3) atom neighbor gather
    gather_sum_kernel<<<(A_N + 3) / 4, gblk>>>(agraph, A_N, tree_msg, msg, nei);

    // 4) pooling + output GEMM with fused segment-sum
    zero_out_kernel<<<(NMOLS * HDIM + 255) / 256, 256>>>(out);
    count_kernel<<<(A_N + 255) / 256, 256>>>(scope);
    prep_w_kernel<<<(256 * 320 + 255) / 256, 256>>>(W_o_w, KO, 320, wthi, wtlo);
    hgemm_kernel<2, KO, 5><<<gridA, 256, HG_SMEM>>>(fatoms, nei, wthi, wtlo, A_N,
                                                    nullptr, W_o_b, scope, out, nullptr);
    finalize_kernel<<<(NMOLS * HDIM + 255) / 256, 256>>>(out);
}